// round 12
// baseline (speedup 1.0000x reference)
#include <cuda_runtime.h>
#include <cuda_fp16.h>
#include <cstdint>

// out[65536,64] = A[65536,512] @ B[512,64]; A[b,i*8+o]=prim_o(x[b,i]) on the fly,
// B = softmax(alphas)*coeffs in-kernel (fp16 ops, fp32 accum, m16n8k16).
// 1024 threads / 32 warps, warp tile m16n64, warp-private double-buffered staging.

#define THREADS    1024
#define PST        20                      // u32 stride per staged row
#define SW_U4      4096                    // W: uint4 per (chunk16, f8, lane32) = 64 KB
#define SP_U32     (64 * PST * 16)         // 32 warps * 2 bufs * 16 rows * PST = 80 KB
#define SMEM_BYTES (SW_U4 * 16 + SP_U32 * 4)   // 147456 B

static __device__ __forceinline__ uint32_t pk(float lo, float hi) {
    __half2 h = __floats2half2_rn(lo, hi);
    return *reinterpret_cast<uint32_t*>(&h);
}

static __device__ __forceinline__ void mma_fp16(float c[4], const uint32_t a[4],
                                                uint32_t b0, uint32_t b1) {
    asm volatile(
        "mma.sync.aligned.m16n8k16.row.col.f32.f16.f16.f32 "
        "{%0,%1,%2,%3}, {%4,%5,%6,%7}, {%8,%9}, {%0,%1,%2,%3};"
        : "+f"(c[0]), "+f"(c[1]), "+f"(c[2]), "+f"(c[3])
        : "r"(a[0]), "r"(a[1]), "r"(a[2]), "r"(a[3]), "r"(b0), "r"(b1));
}

static __device__ __forceinline__ void stage1(uint32_t* p, float xx) {
    float x2 = xx * xx, x3 = x2 * xx;
    float ex = __expf(xx), lg = __logf(xx), sn = __sinf(xx);
    float rc;
    asm("rcp.approx.f32 %0, %1;" : "=f"(rc) : "f"(xx));
    uint4 v;
    v.x = pk(0.0f, xx);
    v.y = pk(x2, x3);
    v.z = pk(ex, lg);
    v.w = pk(rc, sn);
    *(uint4*)p = v;
}

__global__ void __launch_bounds__(THREADS, 1)
darts_kernel(const float* __restrict__ x, const float* __restrict__ alphas,
             const float* __restrict__ coeffs, float* __restrict__ out) {
    extern __shared__ uint32_t sm[];
    uint4*    sW = (uint4*)sm;             // 64 KB: [c16][f8][lane32] = {kk0.b0,kk0.b1,kk1.b0,kk1.b1}
    uint32_t* sP = sm + SW_U4 * 4;         // 80 KB: [warp][buf][row16][PST]

    int tid = threadIdx.x, lane = tid & 31, warp = tid >> 5;
    int qrow = lane >> 2, qcol = lane & 3;

    // ---- build W = softmax(alphas)*coeffs into fragment order (4 ids/thread)
#pragma unroll
    for (int p = 0; p < 4; ++p) {
        int id = tid + p * 1024;
        int i = id >> 6, j = id & 63;
        const float4* av = (const float4*)(alphas + (size_t)id * 8);
        const float4* cv = (const float4*)(coeffs + (size_t)id * 8);
        float4 a0 = av[0], a1 = av[1], c0 = cv[0], c1 = cv[1];
        float e0 = __expf(a0.x), e1 = __expf(a0.y), e2 = __expf(a0.z), e3 = __expf(a0.w);
        float e4 = __expf(a1.x), e5 = __expf(a1.y), e6 = __expf(a1.z), e7 = __expf(a1.w);
        float inv = 1.0f / (e0 + e1 + e2 + e3 + e4 + e5 + e6 + e7);
        float w[8] = {0.0f,            e1 * inv * c0.y, e2 * inv * c0.z, e3 * inv * c0.w,
                      e4 * inv * c1.x, e5 * inv * c1.y, e6 * inv * c1.z, e7 * inv * c1.w};
        int c = i >> 2, kk = (i >> 1) & 1, slot = i & 1, fb = j >> 3;
        // word index = ((c*8+fb)*32 + lane)*4 + kk*2 + slot, lane = (j&7)*4 + q
        uint32_t base = ((c * 8 + fb) * 32 + (j & 7) * 4) * 4 + kk * 2 + slot;
#pragma unroll
        for (int q = 0; q < 4; ++q)
            sm[base + q * 4] = pk(w[2 * q], w[2 * q + 1]);   // FIX: stride 4 (was 16)
    }
    __syncthreads();

    float acc[8][4];
#pragma unroll
    for (int f = 0; f < 8; ++f)
#pragma unroll
        for (int q = 0; q < 4; ++q) acc[f][q] = 0.f;

    // warp owns rows warp*16..+15; lane: row16=lane&15, feature-pair up=lane>>4
    int row16 = lane & 15, up = lane >> 4;
    uint32_t* spw = sP + warp * (2 * 16 * PST);
    const float* xq = x + ((size_t)blockIdx.x * 512 + warp * 16 + row16) * 64 + up * 2;

    float2 xv = *(const float2*)xq;
    for (int c = 0; c < 16; ++c) {
        float2 xn = xv;
        if (c < 15) xn = *(const float2*)(xq + (c + 1) * 4);

        uint32_t* spb = spw + (c & 1) * (16 * PST);
        stage1(spb + row16 * PST + (2 * up) * 4, xv.x);
        stage1(spb + row16 * PST + (2 * up + 1) * 4, xv.y);
        __syncwarp();

        // A fragments for both k-steps (kk=0: u 0,1; kk=1: u 2,3)
        uint32_t a0[4], a1[4];
        {
            const uint32_t* pr0 = spb + qrow * PST + qcol;
            const uint32_t* pr1 = spb + (qrow + 8) * PST + qcol;
            a0[0] = pr0[0];  a0[1] = pr1[0];  a0[2] = pr0[4];  a0[3] = pr1[4];
            a1[0] = pr0[8];  a1[1] = pr1[8];  a1[2] = pr0[12]; a1[3] = pr1[12];
        }
        const uint4* wb = sW + (c * 8) * 32 + lane;
#pragma unroll
        for (int f = 0; f < 8; ++f) {
            uint4 b = wb[f * 32];
            mma_fp16(acc[f], a0, b.x, b.y);
            mma_fp16(acc[f], a1, b.z, b.w);
        }
        xv = xn;
    }

    // ---- epilogue: rows qrow, qrow+8 of this warp's 16-row tile
    size_t r = (size_t)blockIdx.x * 512 + warp * 16 + qrow;
#pragma unroll
    for (int f = 0; f < 8; ++f) {
        int col = f * 8 + qcol * 2;
        *(float2*)(out + r * 64 + col)       = make_float2(acc[f][0], acc[f][1]);
        *(float2*)(out + (r + 8) * 64 + col) = make_float2(acc[f][2], acc[f][3]);
    }
}

extern "C" void kernel_launch(void* const* d_in, const int* in_sizes, int n_in,
                              void* d_out, int out_size) {
    const float* x      = (const float*)d_in[0];   // [65536, 64]
    const float* alphas = (const float*)d_in[1];   // [64, 64, 8]
    const float* coeffs = (const float*)d_in[2];   // [64, 64, 8]
    cudaFuncSetAttribute((const void*)darts_kernel,
                         cudaFuncAttributeMaxDynamicSharedMemorySize, SMEM_BYTES);
    darts_kernel<<<128, THREADS, SMEM_BYTES>>>(x, alphas, coeffs, (float*)d_out);
}

// round 14
// speedup vs baseline: 1.2886x; 1.2886x over previous
#include <cuda_runtime.h>
#include <cuda_fp16.h>
#include <cstdint>

// out[65536,64] = A[65536,512] @ B[512,64]; A[b,i*8+o]=prim_o(x[b,i]) on the fly,
// B = softmax(alphas)*coeffs in-kernel (fp16 ops, fp32 accum, m16n8k16).
// 512 threads / 16 warps, warp tile m32n64, warp-private double-buffered staging,
// XOR-swizzled staging slots (STS.128 conflict-free), uint4 B fragments.

#define THREADS    512
#define PST        20                      // u32 stride per staged row
#define SW_U32     16384                   // W: uint4 per (chunk16, f8, lane32) = 64 KB
#define SP_U32     (512 * PST)             // one stage buffer: 40 KB
#define SMEM_BYTES ((SW_U32 + 2 * SP_U32) * 4)   // 147456 B

static __device__ __forceinline__ uint32_t pk(float lo, float hi) {
    __half2 h = __floats2half2_rn(lo, hi);
    return *reinterpret_cast<uint32_t*>(&h);
}

static __device__ __forceinline__ void mma_fp16(float c[4], const uint32_t a[4],
                                                uint32_t b0, uint32_t b1) {
    asm volatile(
        "mma.sync.aligned.m16n8k16.row.col.f32.f16.f16.f32 "
        "{%0,%1,%2,%3}, {%4,%5,%6,%7}, {%8,%9}, {%0,%1,%2,%3};"
        : "+f"(c[0]), "+f"(c[1]), "+f"(c[2]), "+f"(c[3])
        : "r"(a[0]), "r"(a[1]), "r"(a[2]), "r"(a[3]), "r"(b0), "r"(b1));
}

// one feature's 8 prims as 4 fp16x2 words
static __device__ __forceinline__ uint4 prims(float xx) {
    float x2 = xx * xx, x3 = x2 * xx;
    float ex = __expf(xx), lg = __logf(xx), sn = __sinf(xx);
    float rc;
    asm("rcp.approx.f32 %0, %1;" : "=f"(rc) : "f"(xx));
    uint4 v;
    v.x = pk(0.0f, xx);
    v.y = pk(x2, x3);
    v.z = pk(ex, lg);
    v.w = pk(rc, sn);
    return v;
}

__global__ void __launch_bounds__(THREADS, 1)
darts_kernel(const float* __restrict__ x, const float* __restrict__ alphas,
             const float* __restrict__ coeffs, float* __restrict__ out) {
    extern __shared__ uint32_t sm[];
    uint4*    sW = (uint4*)sm;             // 64 KB: [c16][f8][lane32] = {kk0.b0,kk0.b1,kk1.b0,kk1.b1}
    uint32_t* sP = sm + SW_U32;            // 2 x 40 KB: [buf][row512][PST]

    int tid = threadIdx.x, lane = tid & 31, warp = tid >> 5;
    int qrow = lane >> 2, qcol = lane & 3;

    // ---- build W = softmax(alphas)*coeffs into uint4 fragment order (verified R12)
#pragma unroll
    for (int p = 0; p < 8; ++p) {
        int id = tid + p * 512;
        int i = id >> 6, j = id & 63;
        const float4* av = (const float4*)(alphas + (size_t)id * 8);
        const float4* cv = (const float4*)(coeffs + (size_t)id * 8);
        float4 a0 = av[0], a1 = av[1], c0 = cv[0], c1 = cv[1];
        float e0 = __expf(a0.x), e1 = __expf(a0.y), e2 = __expf(a0.z), e3 = __expf(a0.w);
        float e4 = __expf(a1.x), e5 = __expf(a1.y), e6 = __expf(a1.z), e7 = __expf(a1.w);
        float inv = 1.0f / (e0 + e1 + e2 + e3 + e4 + e5 + e6 + e7);
        float w[8] = {0.0f,            e1 * inv * c0.y, e2 * inv * c0.z, e3 * inv * c0.w,
                      e4 * inv * c1.x, e5 * inv * c1.y, e6 * inv * c1.z, e7 * inv * c1.w};
        int c = i >> 2, kk = (i >> 1) & 1, slot = i & 1, fb = j >> 3;
        uint32_t base = ((c * 8 + fb) * 32 + (j & 7) * 4) * 4 + kk * 2 + slot;
#pragma unroll
        for (int q = 0; q < 4; ++q)
            sm[base + q * 4] = pk(w[2 * q], w[2 * q + 1]);
    }
    __syncthreads();

    float acc[2][8][4];
#pragma unroll
    for (int mt = 0; mt < 2; ++mt)
#pragma unroll
        for (int f = 0; f < 8; ++f)
#pragma unroll
            for (int q = 0; q < 4; ++q) acc[mt][f][q] = 0.f;

    // thread stages row rowA = warp*32+lane; XOR slot swizzle by row group
    int rowA = warp * 32 + lane;
    int lg = (lane >> 3) & 3;                       // row group of staged row
    const float4* xp = (const float4*)(x + ((size_t)blockIdx.x * 512 + rowA) * 64);

    float4 xv = xp[0];
    for (int c = 0; c < 16; ++c) {
        float4 xn = xv;
        if (c < 15) xn = xp[c + 1];                 // prefetch next chunk

        uint32_t* spb = sP + (c & 1) * SP_U32;
        {   // stage 4 features, slot' = u ^ lg  -> STS.128 conflict-free
            uint32_t* pp = spb + rowA * PST;
            *(uint4*)(pp + ((0 ^ lg) << 2)) = prims(xv.x);
            *(uint4*)(pp + ((1 ^ lg) << 2)) = prims(xv.y);
            *(uint4*)(pp + ((2 ^ lg) << 2)) = prims(xv.z);
            *(uint4*)(pp + ((3 ^ lg) << 2)) = prims(xv.w);
        }
        __syncwarp();

        // A fragments: logical word (row, u, q) at row*PST + ((u^g(row))<<2) + q
        uint32_t a0[2][4], a1[2][4];
#pragma unroll
        for (int mt = 0; mt < 2; ++mt) {
            const uint32_t* r0 = spb + (warp * 32 + mt * 16 + qrow) * PST + qcol;
            const uint32_t* r1 = r0 + 8 * PST;
            int g0 = 2 * mt, g1 = 2 * mt + 1;
            a0[mt][0] = r0[(0 ^ g0) << 2];   // kk0, feature u=0
            a0[mt][1] = r1[(0 ^ g1) << 2];
            a0[mt][2] = r0[(1 ^ g0) << 2];   // kk0, feature u=1
            a0[mt][3] = r1[(1 ^ g1) << 2];
            a1[mt][0] = r0[(2 ^ g0) << 2];   // kk1, feature u=2
            a1[mt][1] = r1[(2 ^ g1) << 2];
            a1[mt][2] = r0[(3 ^ g0) << 2];   // kk1, feature u=3
            a1[mt][3] = r1[(3 ^ g1) << 2];
        }

        const uint4* wb = sW + (c * 8) * 32 + lane;
#pragma unroll
        for (int f = 0; f < 8; ++f) {
            uint4 b = wb[f * 32];
            mma_fp16(acc[0][f], a0[0], b.x, b.y);
            mma_fp16(acc[1][f], a0[1], b.x, b.y);
            mma_fp16(acc[0][f], a1[0], b.z, b.w);
            mma_fp16(acc[1][f], a1[1], b.z, b.w);
        }
        xv = xn;
    }

    // ---- epilogue
#pragma unroll
    for (int mt = 0; mt < 2; ++mt) {
        size_t r = (size_t)blockIdx.x * 512 + warp * 32 + mt * 16 + qrow;
#pragma unroll
        for (int f = 0; f < 8; ++f) {
            int col = f * 8 + qcol * 2;
            *(float2*)(out + r * 64 + col)       = make_float2(acc[mt][f][0], acc[mt][f][1]);
            *(float2*)(out + (r + 8) * 64 + col) = make_float2(acc[mt][f][2], acc[mt][f][3]);
        }
    }
}

extern "C" void kernel_launch(void* const* d_in, const int* in_sizes, int n_in,
                              void* d_out, int out_size) {
    const float* x      = (const float*)d_in[0];   // [65536, 64]
    const float* alphas = (const float*)d_in[1];   // [64, 64, 8]
    const float* coeffs = (const float*)d_in[2];   // [64, 64, 8]
    cudaFuncSetAttribute((const void*)darts_kernel,
                         cudaFuncAttributeMaxDynamicSharedMemorySize, SMEM_BYTES);
    darts_kernel<<<128, THREADS, SMEM_BYTES>>>(x, alphas, coeffs, (float*)d_out);
}

// round 15
// speedup vs baseline: 1.5193x; 1.1791x over previous
#include <cuda_runtime.h>
#include <cuda_fp16.h>
#include <cstdint>

// out[65536,64] = A[65536,512] @ B[512,64], A[b, c*64 + s*16 + half*8 + F] =
// prim_{2s+half}(x[b, 8c+F]).  K re-ordered so each thread computes its own
// mma A-fragment directly in registers: NO smem staging, no mainloop barriers.
// B = softmax(alphas)*coeffs, prebuilt in fragment layout by prep kernel.

#define NW 16384                     // W words: [c8][s4][fp4][lane32][4] = 64 KB
__device__ uint32_t g_W[NW];

static __device__ __forceinline__ uint32_t pk(float lo, float hi) {
    __half2 h = __floats2half2_rn(lo, hi);
    return *reinterpret_cast<uint32_t*>(&h);
}

static __device__ __forceinline__ void mma16(float c[4], uint32_t a0, uint32_t a1,
                                             uint32_t a2, uint32_t a3,
                                             uint32_t b0, uint32_t b1) {
    asm volatile(
        "mma.sync.aligned.m16n8k16.row.col.f32.f16.f16.f32 "
        "{%0,%1,%2,%3}, {%4,%5,%6,%7}, {%8,%9}, {%0,%1,%2,%3};"
        : "+f"(c[0]), "+f"(c[1]), "+f"(c[2]), "+f"(c[3])
        : "r"(a0), "r"(a1), "r"(a2), "r"(a3), "r"(b0), "r"(b1));
}
static __device__ __forceinline__ void mma8(float c[4], uint32_t a0, uint32_t a1,
                                            uint32_t b0) {
    asm volatile(
        "mma.sync.aligned.m16n8k8.row.col.f32.f16.f16.f32 "
        "{%0,%1,%2,%3}, {%4,%5}, {%6}, {%0,%1,%2,%3};"
        : "+f"(c[0]), "+f"(c[1]), "+f"(c[2]), "+f"(c[3])
        : "r"(a0), "r"(a1), "r"(b0));
}

// ---------------------------------------------------------------------------
// prep: build W into fragment layout. 2048 threads, thread = (i-pair, j).
// word(c,s,fp,lane,(fb&1)*2+slot) = pk(w[8c+2q][j][2s+slot], w[8c+2q+1][j][2s+slot])
//   lane = (j&7)*4 + q
// ---------------------------------------------------------------------------
__global__ void prep_w(const float* __restrict__ alphas,
                       const float* __restrict__ coeffs) {
    int id = blockIdx.x * blockDim.x + threadIdx.x;   // 0..2047
    int ip = id >> 6, j = id & 63;
    float w[2][8];
#pragma unroll
    for (int e = 0; e < 2; ++e) {
        int i = ip * 2 + e;
        const float4* av = (const float4*)(alphas + ((size_t)i * 64 + j) * 8);
        const float4* cv = (const float4*)(coeffs + ((size_t)i * 64 + j) * 8);
        float4 a0 = av[0], a1 = av[1], c0 = cv[0], c1 = cv[1];
        float e0 = __expf(a0.x), e1 = __expf(a0.y), e2 = __expf(a0.z), e3 = __expf(a0.w);
        float e4 = __expf(a1.x), e5 = __expf(a1.y), e6 = __expf(a1.z), e7 = __expf(a1.w);
        float inv = 1.0f / (e0 + e1 + e2 + e3 + e4 + e5 + e6 + e7);
        w[e][0] = 0.0f;            w[e][1] = e1 * inv * c0.y;
        w[e][2] = e2 * inv * c0.z; w[e][3] = e3 * inv * c0.w;
        w[e][4] = e4 * inv * c1.x; w[e][5] = e5 * inv * c1.y;
        w[e][6] = e6 * inv * c1.z; w[e][7] = e7 * inv * c1.w;
    }
    int c = ip >> 2, q = ip & 3;
    int lane = (j & 7) * 4 + q, fb = j >> 3;
#pragma unroll
    for (int o = 0; o < 8; ++o) {
        int s = o >> 1, slot = o & 1;
        g_W[(((c * 4 + s) * 4 + (fb >> 1)) * 32 + lane) * 4 + (fb & 1) * 2 + slot] =
            pk(w[0][o], w[1][o]);
    }
}

// ---------------------------------------------------------------------------
// main: 256 CTAs x 256 threads, 2 CTAs/SM. Warp tile m32n64, 256 rows/CTA.
// ---------------------------------------------------------------------------
#define MSTEP(B, sel0, sel1)                                                  \
    do {                                                                      \
        mma16(acc[0][2 * (&B - Bv)], A0[0], A0[1], A1[0], A1[1], B.sel0, B.sel1); \
    } while (0)

__global__ void __launch_bounds__(256, 2)
darts_kernel(const float* __restrict__ x, float* __restrict__ out) {
    extern __shared__ uint32_t sW[];
    int tid = threadIdx.x, lane = tid & 31, warp = tid >> 5;
    int qrow = lane >> 2, qcol = lane & 3;

    // copy W (64 KB) global -> shared, coalesced
    {
        const uint4* g4 = (const uint4*)g_W;
        uint4* s4 = (uint4*)sW;
#pragma unroll
        for (int k = 0; k < 16; ++k) s4[tid + k * 256] = g4[tid + k * 256];
    }
    __syncthreads();

    float acc[2][8][4];
#pragma unroll
    for (int mt = 0; mt < 2; ++mt)
#pragma unroll
        for (int f = 0; f < 8; ++f)
#pragma unroll
            for (int q = 0; q < 4; ++q) acc[mt][f][q] = 0.f;

    // thread's 4 rows: qrow + {0,8,16,24} within warp's 32-row tile
    size_t grow = (size_t)blockIdx.x * 256 + warp * 32 + qrow;
    const float* px = x + grow * 64 + 2 * qcol;

    float2 xc[4], xn[4];
#pragma unroll
    for (int k = 0; k < 4; ++k) xc[k] = *(const float2*)(px + k * 512);

#pragma unroll 2
    for (int c = 0; c < 8; ++c) {
        if (c < 7) {
#pragma unroll
            for (int k = 0; k < 4; ++k)
                xn[k] = *(const float2*)(px + k * 512 + (c + 1) * 8);
        }
        const uint4* wb = (const uint4*)sW + (c * 16) * 32 + lane;
        uint32_t A0[4], A1[4];

        // ---- s=0: ops (none, linear). k-low half is all-zero -> k8 mma on high half.
        {
#pragma unroll
            for (int k = 0; k < 4; ++k) A1[k] = pk(xc[k].x, xc[k].y);
            uint4 B0 = wb[0 * 32], B1 = wb[1 * 32], B2 = wb[2 * 32], B3 = wb[3 * 32];
            mma8(acc[0][0], A1[0], A1[1], B0.y); mma8(acc[1][0], A1[2], A1[3], B0.y);
            mma8(acc[0][1], A1[0], A1[1], B0.w); mma8(acc[1][1], A1[2], A1[3], B0.w);
            mma8(acc[0][2], A1[0], A1[1], B1.y); mma8(acc[1][2], A1[2], A1[3], B1.y);
            mma8(acc[0][3], A1[0], A1[1], B1.w); mma8(acc[1][3], A1[2], A1[3], B1.w);
            mma8(acc[0][4], A1[0], A1[1], B2.y); mma8(acc[1][4], A1[2], A1[3], B2.y);
            mma8(acc[0][5], A1[0], A1[1], B2.w); mma8(acc[1][5], A1[2], A1[3], B2.w);
            mma8(acc[0][6], A1[0], A1[1], B3.y); mma8(acc[1][6], A1[2], A1[3], B3.y);
            mma8(acc[0][7], A1[0], A1[1], B3.w); mma8(acc[1][7], A1[2], A1[3], B3.w);
        }
        // ---- s=1: ops (x^2, x^3)
        {
#pragma unroll
            for (int k = 0; k < 4; ++k) {
                float a = xc[k].x, b = xc[k].y;
                float a2 = a * a, b2 = b * b;
                A0[k] = pk(a2, b2);
                A1[k] = pk(a2 * a, b2 * b);
            }
            uint4 B0 = wb[4 * 32], B1 = wb[5 * 32], B2 = wb[6 * 32], B3 = wb[7 * 32];
            mma16(acc[0][0], A0[0], A0[1], A1[0], A1[1], B0.x, B0.y);
            mma16(acc[1][0], A0[2], A0[3], A1[2], A1[3], B0.x, B0.y);
            mma16(acc[0][1], A0[0], A0[1], A1[0], A1[1], B0.z, B0.w);
            mma16(acc[1][1], A0[2], A0[3], A1[2], A1[3], B0.z, B0.w);
            mma16(acc[0][2], A0[0], A0[1], A1[0], A1[1], B1.x, B1.y);
            mma16(acc[1][2], A0[2], A0[3], A1[2], A1[3], B1.x, B1.y);
            mma16(acc[0][3], A0[0], A0[1], A1[0], A1[1], B1.z, B1.w);
            mma16(acc[1][3], A0[2], A0[3], A1[2], A1[3], B1.z, B1.w);
            mma16(acc[0][4], A0[0], A0[1], A1[0], A1[1], B2.x, B2.y);
            mma16(acc[1][4], A0[2], A0[3], A1[2], A1[3], B2.x, B2.y);
            mma16(acc[0][5], A0[0], A0[1], A1[0], A1[1], B2.z, B2.w);
            mma16(acc[1][5], A0[2], A0[3], A1[2], A1[3], B2.z, B2.w);
            mma16(acc[0][6], A0[0], A0[1], A1[0], A1[1], B3.x, B3.y);
            mma16(acc[1][6], A0[2], A0[3], A1[2], A1[3], B3.x, B3.y);
            mma16(acc[0][7], A0[0], A0[1], A1[0], A1[1], B3.z, B3.w);
            mma16(acc[1][7], A0[2], A0[3], A1[2], A1[3], B3.z, B3.w);
        }
        // ---- s=2: ops (exp, ln)
        {
#pragma unroll
            for (int k = 0; k < 4; ++k) {
                A0[k] = pk(__expf(xc[k].x), __expf(xc[k].y));
                A1[k] = pk(__logf(xc[k].x), __logf(xc[k].y));
            }
            uint4 B0 = wb[8 * 32], B1 = wb[9 * 32], B2 = wb[10 * 32], B3 = wb[11 * 32];
            mma16(acc[0][0], A0[0], A0[1], A1[0], A1[1], B0.x, B0.y);
            mma16(acc[1][0], A0[2], A0[3], A1[2], A1[3], B0.x, B0.y);
            mma16(acc[0][1], A0[0], A0[1], A1[0], A1[1], B0.z, B0.w);
            mma16(acc[1][1], A0[2], A0[3], A1[2], A1[3], B0.z, B0.w);
            mma16(acc[0][2], A0[0], A0[1], A1[0], A1[1], B1.x, B1.y);
            mma16(acc[1][2], A0[2], A0[3], A1[2], A1[3], B1.x, B1.y);
            mma16(acc[0][3], A0[0], A0[1], A1[0], A1[1], B1.z, B1.w);
            mma16(acc[1][3], A0[2], A0[3], A1[2], A1[3], B1.z, B1.w);
            mma16(acc[0][4], A0[0], A0[1], A1[0], A1[1], B2.x, B2.y);
            mma16(acc[1][4], A0[2], A0[3], A1[2], A1[3], B2.x, B2.y);
            mma16(acc[0][5], A0[0], A0[1], A1[0], A1[1], B2.z, B2.w);
            mma16(acc[1][5], A0[2], A0[3], A1[2], A1[3], B2.z, B2.w);
            mma16(acc[0][6], A0[0], A0[1], A1[0], A1[1], B3.x, B3.y);
            mma16(acc[1][6], A0[2], A0[3], A1[2], A1[3], B3.x, B3.y);
            mma16(acc[0][7], A0[0], A0[1], A1[0], A1[1], B3.z, B3.w);
            mma16(acc[1][7], A0[2], A0[3], A1[2], A1[3], B3.z, B3.w);
        }
        // ---- s=3: ops (1/x, sin)
        {
#pragma unroll
            for (int k = 0; k < 4; ++k) {
                float r0, r1;
                asm("rcp.approx.f32 %0, %1;" : "=f"(r0) : "f"(xc[k].x));
                asm("rcp.approx.f32 %0, %1;" : "=f"(r1) : "f"(xc[k].y));
                A0[k] = pk(r0, r1);
                A1[k] = pk(__sinf(xc[k].x), __sinf(xc[k].y));
            }
            uint4 B0 = wb[12 * 32], B1 = wb[13 * 32], B2 = wb[14 * 32], B3 = wb[15 * 32];
            mma16(acc[0][0], A0[0], A0[1], A1[0], A1[1], B0.x, B0.y);
            mma16(acc[1][0], A0[2], A0[3], A1[2], A1[3], B0.x, B0.y);
            mma16(acc[0][1], A0[0], A0[1], A1[0], A1[1], B0.z, B0.w);
            mma16(acc[1][1], A0[2], A0[3], A1[2], A1[3], B0.z, B0.w);
            mma16(acc[0][2], A0[0], A0[1], A1[0], A1[1], B1.x, B1.y);
            mma16(acc[1][2], A0[2], A0[3], A1[2], A1[3], B1.x, B1.y);
            mma16(acc[0][3], A0[0], A0[1], A1[0], A1[1], B1.z, B1.w);
            mma16(acc[1][3], A0[2], A0[3], A1[2], A1[3], B1.z, B1.w);
            mma16(acc[0][4], A0[0], A0[1], A1[0], A1[1], B2.x, B2.y);
            mma16(acc[1][4], A0[2], A0[3], A1[2], A1[3], B2.x, B2.y);
            mma16(acc[0][5], A0[0], A0[1], A1[0], A1[1], B2.z, B2.w);
            mma16(acc[1][5], A0[2], A0[3], A1[2], A1[3], B2.z, B2.w);
            mma16(acc[0][6], A0[0], A0[1], A1[0], A1[1], B3.x, B3.y);
            mma16(acc[1][6], A0[2], A0[3], A1[2], A1[3], B3.x, B3.y);
            mma16(acc[0][7], A0[0], A0[1], A1[0], A1[1], B3.z, B3.w);
            mma16(acc[1][7], A0[2], A0[3], A1[2], A1[3], B3.z, B3.w);
        }
#pragma unroll
        for (int k = 0; k < 4; ++k) xc[k] = xn[k];
    }

    // ---- epilogue (same verified C layout)
#pragma unroll
    for (int mt = 0; mt < 2; ++mt) {
        size_t r = (size_t)blockIdx.x * 256 + warp * 32 + mt * 16 + qrow;
#pragma unroll
        for (int f = 0; f < 8; ++f) {
            int col = f * 8 + qcol * 2;
            *(float2*)(out + r * 64 + col)       = make_float2(acc[mt][f][0], acc[mt][f][1]);
            *(float2*)(out + (r + 8) * 64 + col) = make_float2(acc[mt][f][2], acc[mt][f][3]);
        }
    }
}

extern "C" void kernel_launch(void* const* d_in, const int* in_sizes, int n_in,
                              void* d_out, int out_size) {
    const float* x      = (const float*)d_in[0];   // [65536, 64]
    const float* alphas = (const float*)d_in[1];   // [64, 64, 8]
    const float* coeffs = (const float*)d_in[2];   // [64, 64, 8]
    cudaFuncSetAttribute((const void*)darts_kernel,
                         cudaFuncAttributeMaxDynamicSharedMemorySize, 65536);
    prep_w<<<8, 256>>>(alphas, coeffs);
    darts_kernel<<<256, 256, 65536>>>(x, (float*)d_out);
}